// round 3
// baseline (speedup 1.0000x reference)
#include <cuda_runtime.h>
#include <cstdint>
#include <cstddef>

// ============================================================================
// PoolingRetriever collapses to: out = x @ (Wo@Wv)^T + (Wo@bv + bo)
//   x: [65536, 768] f32   M = Wo@Wv: [768, 768]   out: [65536, 768] f32
// tcgen05 is unavailable (harness PTX target is compute_103, not 103a), so
// this is an Ampere-style tf32 mma.sync GEMM with a cp.async pipeline.
// ============================================================================

#define DIMN   768
#define NBATCH 65536

__device__ float g_M[DIMN * DIMN];   // M[j,k] = sum_p Wo[j,p]*Wv[p,k], RNE tf32
__device__ float g_c[DIMN];          // c[j]   = bo[j] + sum_p Wo[j,p]*bv[p]

// ---------------------------------------------------------------------------
// Kernel 0: c[j] = bo[j] + sum_p Wo[j,p] * bv[p]          (1 block, 768 thr)
// ---------------------------------------------------------------------------
__global__ void build_c_kernel(const float* __restrict__ Wo,
                               const float* __restrict__ bv,
                               const float* __restrict__ bo) {
    int j = threadIdx.x;
    if (j < DIMN) {
        float s = bo[j];
        #pragma unroll 8
        for (int p = 0; p < 64; p++) s += Wo[j * 64 + p] * bv[p];
        g_c[j] = s;
    }
}

// ---------------------------------------------------------------------------
// Kernel 1: M[j,k] = RNE_tf32( sum_p Wo[j,p] * Wv[p,k] )  (96 blocks x 768)
// Pre-rounding B to tf32 (RNE) keeps mma input error zero-mean.
// ---------------------------------------------------------------------------
__global__ void build_M_kernel(const float* __restrict__ Wo,
                               const float* __restrict__ Wv) {
    __shared__ float wo_s[8 * 64];
    int j0 = blockIdx.x * 8;
    int t = threadIdx.x;                 // 768 threads, t = k
    if (t < 512) wo_s[t] = Wo[j0 * 64 + t];
    __syncthreads();

    float acc[8];
    #pragma unroll
    for (int j = 0; j < 8; j++) acc[j] = 0.0f;

    #pragma unroll 4
    for (int p = 0; p < 64; p++) {
        float wv = Wv[p * DIMN + t];
        #pragma unroll
        for (int j = 0; j < 8; j++) acc[j] += wo_s[j * 64 + p] * wv;
    }
    #pragma unroll
    for (int j = 0; j < 8; j++) {
        uint32_t u;
        asm("cvt.rna.tf32.f32 %0, %1;" : "=r"(u) : "f"(acc[j]));
        g_M[(j0 + j) * DIMN + t] = __uint_as_float(u);
    }
}

// ---------------------------------------------------------------------------
// Kernel 2: out = x @ M^T + c
//   CTA tile 128M x 128N, K-stage 32, 4-stage cp.async pipeline.
//   8 warps (2 m x 4 n), warp tile 64x32, mma.m16n8k8 tf32.
//   SW128-style XOR swizzle => conflict-free LDS for both store and frag load.
// ---------------------------------------------------------------------------
static constexpr int BM = 128, BN = 128, BK = 32;
static constexpr int STAGES = 4;
static constexpr int STAGE_BYTES = (BM + BN) * BK * 4;   // 32768
static constexpr int GEMM_SMEM = STAGES * STAGE_BYTES;   // 131072
static constexpr int KTILES = DIMN / BK;                 // 24

__device__ __forceinline__ uint32_t smem_u32(const void* p) {
    uint32_t a;
    asm("{ .reg .u64 t; cvta.to.shared.u64 t, %1; cvt.u32.u64 %0, t; }"
        : "=r"(a) : "l"(p));
    return a;
}

__device__ __forceinline__ void cp_async16(uint32_t dst, const void* src) {
    asm volatile("cp.async.cg.shared.global [%0], [%1], 16;"
                 :: "r"(dst), "l"(src) : "memory");
}

__device__ __forceinline__ uint32_t cvt_tf32(uint32_t raw) {
    uint32_t u;
    asm("cvt.rna.tf32.f32 %0, %1;" : "=r"(u) : "f"(__uint_as_float(raw)));
    return u;
}

__device__ __forceinline__ void mma_tf32(float* c, const uint32_t* a,
                                         const uint32_t* b) {
    asm volatile(
        "mma.sync.aligned.m16n8k8.row.col.f32.tf32.tf32.f32 "
        "{%0,%1,%2,%3}, {%4,%5,%6,%7}, {%8,%9}, {%0,%1,%2,%3};"
        : "+f"(c[0]), "+f"(c[1]), "+f"(c[2]), "+f"(c[3])
        : "r"(a[0]), "r"(a[1]), "r"(a[2]), "r"(a[3]), "r"(b[0]), "r"(b[1]));
}

// One stage of global->shared loads: 2048 16B chunks over 256 threads.
__device__ __forceinline__ void load_stage(uint32_t sbase,
                                           const float* __restrict__ x,
                                           int m0, int n0, int kt, int tid) {
    const int kbase = kt * BK;
    #pragma unroll
    for (int i = 0; i < 8; i++) {
        const int c = tid + i * 256;
        const int o = c & 7;                       // 16B chunk within 128B row
        if (c < 1024) {                            // A: 128 rows of x
            const int r = c >> 3;
            const float* src = x + (size_t)(m0 + r) * DIMN + kbase + o * 4;
            cp_async16(sbase + r * 128 + ((o * 16) ^ ((r & 7) << 4)), src);
        } else {                                   // B: 128 rows of M
            const int r = (c - 1024) >> 3;
            const float* src = g_M + (size_t)(n0 + r) * DIMN + kbase + o * 4;
            cp_async16(sbase + 16384 + r * 128 + ((o * 16) ^ ((r & 7) << 4)), src);
        }
    }
    asm volatile("cp.async.commit_group;" ::: "memory");
}

__global__ void __launch_bounds__(256, 1)
gemm_tf32_kernel(const float* __restrict__ x, float* __restrict__ out) {
    extern __shared__ uint8_t smem[];
    const uint32_t sb0 = smem_u32(smem);

    const int tid    = threadIdx.x;
    const int wid    = tid >> 5;
    const int lane   = tid & 31;
    const int grp    = lane >> 2;          // 0..7
    const int tig    = lane & 3;           // 0..3
    const int warp_m = wid & 1;            // 2 m-warps
    const int warp_n = wid >> 1;           // 4 n-warps

    const int m0 = (blockIdx.x / 6) * BM;  // n fastest => 6 CTAs share x tile
    const int n0 = (blockIdx.x % 6) * BN;

    float acc[4][4][4];
    #pragma unroll
    for (int mt = 0; mt < 4; mt++)
        #pragma unroll
        for (int nt = 0; nt < 4; nt++)
            #pragma unroll
            for (int i = 0; i < 4; i++) acc[mt][nt][i] = 0.0f;

    // prologue: fill 3 stages
    #pragma unroll
    for (int s = 0; s < STAGES - 1; s++)
        load_stage(sb0 + s * STAGE_BYTES, x, m0, n0, s, tid);

    for (int kt = 0; kt < KTILES; kt++) {
        asm volatile("cp.async.wait_group %0;" :: "n"(STAGES - 2) : "memory");
        __syncthreads();

        // issue next stage into the buffer freed by iteration kt-1
        if (kt + STAGES - 1 < KTILES)
            load_stage(sb0 + ((kt + STAGES - 1) % STAGES) * STAGE_BYTES,
                       x, m0, n0, kt + STAGES - 1, tid);
        else
            asm volatile("cp.async.commit_group;" ::: "memory");

        // compute on stage kt
        const uint8_t* As = smem + (kt % STAGES) * STAGE_BYTES;
        const uint8_t* Bs = As + 16384;

        #pragma unroll
        for (int ks = 0; ks < 4; ks++) {
            const int k0 = ks * 8;
            uint32_t a[4][4];
            #pragma unroll
            for (int mt = 0; mt < 4; mt++) {
                const int r = warp_m * 64 + mt * 16 + grp;
                const uint32_t xr = (uint32_t)((r & 7) << 4);
                const uint32_t cA = ((uint32_t)((k0 + tig) * 4)) ^ xr;
                const uint32_t cB = ((uint32_t)((k0 + tig + 4) * 4)) ^ xr;
                a[mt][0] = cvt_tf32(*(const uint32_t*)(As + r * 128 + cA));
                a[mt][1] = cvt_tf32(*(const uint32_t*)(As + (r + 8) * 128 + cA));
                a[mt][2] = cvt_tf32(*(const uint32_t*)(As + r * 128 + cB));
                a[mt][3] = cvt_tf32(*(const uint32_t*)(As + (r + 8) * 128 + cB));
            }
            uint32_t b[4][2];
            #pragma unroll
            for (int nt = 0; nt < 4; nt++) {
                const int rn = warp_n * 32 + nt * 8 + grp;
                const uint32_t xr = (uint32_t)((rn & 7) << 4);
                b[nt][0] = *(const uint32_t*)(Bs + rn * 128 +
                                              (((uint32_t)((k0 + tig) * 4)) ^ xr));
                b[nt][1] = *(const uint32_t*)(Bs + rn * 128 +
                                              (((uint32_t)((k0 + tig + 4) * 4)) ^ xr));
            }
            #pragma unroll
            for (int mt = 0; mt < 4; mt++)
                #pragma unroll
                for (int nt = 0; nt < 4; nt++)
                    mma_tf32(acc[mt][nt], a[mt], b[nt]);
        }
    }

    // epilogue: bias add + float2 stores
    #pragma unroll
    for (int mt = 0; mt < 4; mt++) {
        const int row = m0 + warp_m * 64 + mt * 16 + grp;
        #pragma unroll
        for (int nt = 0; nt < 4; nt++) {
            const int col = n0 + warp_n * 32 + nt * 8 + tig * 2;
            const float2 cb = *(const float2*)(g_c + col);
            float2 v0, v1;
            v0.x = acc[mt][nt][0] + cb.x;
            v0.y = acc[mt][nt][1] + cb.y;
            v1.x = acc[mt][nt][2] + cb.x;
            v1.y = acc[mt][nt][3] + cb.y;
            *(float2*)(out + (size_t)row * DIMN + col) = v0;
            *(float2*)(out + (size_t)(row + 8) * DIMN + col) = v1;
        }
    }
}

// ---------------------------------------------------------------------------
// kernel_launch
// inputs: 0=x, 1=q_state, 2=Wq, 3=bq, 4=Wk, 5=bk, 6=Wv, 7=bv, 8=Wo, 9=bo
// ---------------------------------------------------------------------------
extern "C" void kernel_launch(void* const* d_in, const int* in_sizes, int n_in,
                              void* d_out, int out_size) {
    const float* x  = (const float*)d_in[0];
    const float* Wv = (const float*)d_in[6];
    const float* bv = (const float*)d_in[7];
    const float* Wo = (const float*)d_in[8];
    const float* bo = (const float*)d_in[9];
    float* out = (float*)d_out;

    build_c_kernel<<<1, DIMN>>>(Wo, bv, bo);
    build_M_kernel<<<DIMN / 8, DIMN>>>(Wo, Wv);

    cudaFuncSetAttribute(gemm_tf32_kernel,
                         cudaFuncAttributeMaxDynamicSharedMemorySize, GEMM_SMEM);
    gemm_tf32_kernel<<<(NBATCH / BM) * (DIMN / BN), 256, GEMM_SMEM>>>(x, out);
}

// round 5
// speedup vs baseline: 1.9137x; 1.9137x over previous
#include <cuda_runtime.h>
#include <cuda_fp16.h>
#include <cstdint>
#include <cstddef>

// ============================================================================
// PoolingRetriever collapses to: out = x @ (Wo@Wv)^T + (Wo@bv + bo)
//   x: [65536, 768] f32   M = Wo@Wv: [768, 768]   out: [65536, 768] f32
// fp16 mma.sync.m16n8k16 path (2x MACs/instr vs tf32 m16n8k8, which
// measured at the 256 MAC/cyc/SM quarter-rate floor => 552us).
// x and M are RNE-converted to fp16 (zero-mean operand error), f32 accumulate.
// ============================================================================

#define DIMN   768
#define NBATCH 65536

__device__ __half g_Xh[(size_t)NBATCH * DIMN];  // x in fp16 (100.7 MB)
__device__ __half g_Mh[DIMN * DIMN];            // M = Wo@Wv in fp16
__device__ float  g_c[DIMN];                    // c = bo + Wo@bv

// ---------------------------------------------------------------------------
// Kernel 0: convert x (f32 -> fp16 RNE), 4 elements/thread
// ---------------------------------------------------------------------------
__global__ void conv_x_kernel(const float* __restrict__ x) {
    const size_t i = ((size_t)blockIdx.x * 256 + threadIdx.x) * 4;
    const float4 v = *reinterpret_cast<const float4*>(x + i);
    __half2 h0 = __floats2half2_rn(v.x, v.y);
    __half2 h1 = __floats2half2_rn(v.z, v.w);
    uint2 p;
    p.x = *reinterpret_cast<uint32_t*>(&h0);
    p.y = *reinterpret_cast<uint32_t*>(&h1);
    *reinterpret_cast<uint2*>(&g_Xh[i]) = p;
}

// ---------------------------------------------------------------------------
// Kernel 1: c[j] = bo[j] + sum_p Wo[j,p] * bv[p]          (1 block, 768 thr)
// ---------------------------------------------------------------------------
__global__ void build_c_kernel(const float* __restrict__ Wo,
                               const float* __restrict__ bv,
                               const float* __restrict__ bo) {
    int j = threadIdx.x;
    if (j < DIMN) {
        float s = bo[j];
        #pragma unroll 8
        for (int p = 0; p < 64; p++) s += Wo[j * 64 + p] * bv[p];
        g_c[j] = s;
    }
}

// ---------------------------------------------------------------------------
// Kernel 2: M[j,k] = RNE_fp16( sum_p Wo[j,p] * Wv[p,k] )  (96 blocks x 768)
// ---------------------------------------------------------------------------
__global__ void build_M_kernel(const float* __restrict__ Wo,
                               const float* __restrict__ Wv) {
    __shared__ float wo_s[8 * 64];
    int j0 = blockIdx.x * 8;
    int t = threadIdx.x;                 // 768 threads, t = k
    if (t < 512) wo_s[t] = Wo[j0 * 64 + t];
    __syncthreads();

    float acc[8];
    #pragma unroll
    for (int j = 0; j < 8; j++) acc[j] = 0.0f;

    #pragma unroll 4
    for (int p = 0; p < 64; p++) {
        float wv = Wv[p * DIMN + t];
        #pragma unroll
        for (int j = 0; j < 8; j++) acc[j] += wo_s[j * 64 + p] * wv;
    }
    #pragma unroll
    for (int j = 0; j < 8; j++)
        g_Mh[(j0 + j) * DIMN + t] = __float2half_rn(acc[j]);
}

// ---------------------------------------------------------------------------
// Kernel 3: out = Xh @ Mh^T + c   (fp16 mma.m16n8k16, f32 accum)
//   CTA 128M x 128N, BK=64 (128B fp16 rows => native SW128 swizzle).
//   3-stage cp.async pipeline, 8 warps (2m x 4n), warp tile 64x32.
//   Fragments via ldmatrix.x4 (A: 4/ks, B: 2/ks), 16 mma per K16-slice.
// ---------------------------------------------------------------------------
static constexpr int BM = 128, BN = 128, BK = 64;
static constexpr int STAGES = 3;
static constexpr int STAGE_BYTES = (BM + BN) * BK * 2;   // 32768
static constexpr int GEMM_SMEM = STAGES * STAGE_BYTES;   // 98304
static constexpr int KTILES = DIMN / BK;                 // 12

__device__ __forceinline__ uint32_t smem_u32(const void* p) {
    uint32_t a;
    asm("{ .reg .u64 t; cvta.to.shared.u64 t, %1; cvt.u32.u64 %0, t; }"
        : "=r"(a) : "l"(p));
    return a;
}
__device__ __forceinline__ void cp_async16(uint32_t dst, const void* src) {
    asm volatile("cp.async.cg.shared.global [%0], [%1], 16;"
                 :: "r"(dst), "l"(src) : "memory");
}
__device__ __forceinline__ void ldmatrix_x4(uint32_t& r0, uint32_t& r1,
                                            uint32_t& r2, uint32_t& r3,
                                            uint32_t addr) {
    asm volatile("ldmatrix.sync.aligned.m8n8.x4.shared.b16 {%0,%1,%2,%3}, [%4];"
                 : "=r"(r0), "=r"(r1), "=r"(r2), "=r"(r3) : "r"(addr));
}
__device__ __forceinline__ void mma_f16(float* c, const uint32_t* a,
                                        const uint32_t* b) {
    asm volatile(
        "mma.sync.aligned.m16n8k16.row.col.f32.f16.f16.f32 "
        "{%0,%1,%2,%3}, {%4,%5,%6,%7}, {%8,%9}, {%0,%1,%2,%3};"
        : "+f"(c[0]), "+f"(c[1]), "+f"(c[2]), "+f"(c[3])
        : "r"(a[0]), "r"(a[1]), "r"(a[2]), "r"(a[3]), "r"(b[0]), "r"(b[1]));
}

// One stage: A 128x64 fp16 + B 128x64 fp16 = 2048 16B chunks / 256 threads.
__device__ __forceinline__ void load_stage(uint32_t sbase, int m0, int n0,
                                           int kt, int tid) {
    const int kbase = kt * BK;                   // in halves
    #pragma unroll
    for (int i = 0; i < 8; i++) {
        const int c = tid + i * 256;
        const int o = c & 7;                     // 16B chunk (8 halves) in row
        if (c < 1024) {                          // A
            const int r = c >> 3;
            const __half* src = g_Xh + (size_t)(m0 + r) * DIMN + kbase + o * 8;
            cp_async16(sbase + r * 128 + ((o * 16) ^ ((r & 7) << 4)), src);
        } else {                                 // B
            const int r = (c - 1024) >> 3;
            const __half* src = g_Mh + (size_t)(n0 + r) * DIMN + kbase + o * 8;
            cp_async16(sbase + 16384 + r * 128 + ((o * 16) ^ ((r & 7) << 4)), src);
        }
    }
    asm volatile("cp.async.commit_group;" ::: "memory");
}

__global__ void __launch_bounds__(256, 2)
gemm_f16_kernel(float* __restrict__ out) {
    extern __shared__ uint8_t smem[];
    const uint32_t sb0 = smem_u32(smem);

    const int tid    = threadIdx.x;
    const int wid    = tid >> 5;
    const int lane   = tid & 31;
    const int grp    = lane >> 2;          // 0..7
    const int tig    = lane & 3;           // 0..3
    const int warp_m = wid & 1;            // 2 m-warps (64 rows each)
    const int warp_n = wid >> 1;           // 4 n-warps (32 cols each)

    const int m0 = (blockIdx.x / 6) * BM;  // n fastest: 6 CTAs share A in L2
    const int n0 = (blockIdx.x % 6) * BN;

    float acc[4][4][4];
    #pragma unroll
    for (int mt = 0; mt < 4; mt++)
        #pragma unroll
        for (int nt = 0; nt < 4; nt++)
            #pragma unroll
            for (int i = 0; i < 4; i++) acc[mt][nt][i] = 0.0f;

    // ldmatrix per-lane source addresses (row part), computed once.
    // A x4: rows r0 + (lane&15), k-byte base + (lane>>4)*16
    const int a_row_in16 = lane & 15;
    const int a_koff     = (lane >> 4) * 16;
    // B x4: n-row n0w + (lane&7) + ((lane&16)?8:0), k-byte base + ((lane&8)?16:0)
    const int b_row_in16 = (lane & 7) + ((lane & 16) ? 8 : 0);
    const int b_koff     = (lane & 8) ? 16 : 0;

    // prologue
    #pragma unroll
    for (int s = 0; s < STAGES - 1; s++)
        load_stage(sb0 + s * STAGE_BYTES, m0, n0, s, tid);

    for (int kt = 0; kt < KTILES; kt++) {
        asm volatile("cp.async.wait_group %0;" :: "n"(STAGES - 2) : "memory");
        __syncthreads();

        if (kt + STAGES - 1 < KTILES)
            load_stage(sb0 + ((kt + STAGES - 1) % STAGES) * STAGE_BYTES,
                       m0, n0, kt + STAGES - 1, tid);
        else
            asm volatile("cp.async.commit_group;" ::: "memory");

        const uint32_t As = sb0 + (kt % STAGES) * STAGE_BYTES;
        const uint32_t Bs = As + 16384;

        #pragma unroll
        for (int ks = 0; ks < 4; ks++) {       // 4 x K16
            const int kb = ks * 32;            // byte offset of K16 slice
            uint32_t a[4][4];
            #pragma unroll
            for (int mt = 0; mt < 4; mt++) {
                const int r = warp_m * 64 + mt * 16 + a_row_in16;
                const uint32_t col = (uint32_t)(kb + a_koff) ^ ((r & 7) << 4);
                ldmatrix_x4(a[mt][0], a[mt][1], a[mt][2], a[mt][3],
                            As + r * 128 + col);
            }
            uint32_t b[4][2];
            #pragma unroll
            for (int p = 0; p < 2; p++) {      // each x4 covers 2 nt tiles
                const int rn = warp_n * 32 + p * 16 + b_row_in16;
                const uint32_t col = (uint32_t)(kb + b_koff) ^ ((rn & 7) << 4);
                uint32_t r0, r1, r2, r3;
                ldmatrix_x4(r0, r1, r2, r3, Bs + rn * 128 + col);
                b[2 * p][0] = r0;  b[2 * p][1] = r1;
                b[2 * p + 1][0] = r2;  b[2 * p + 1][1] = r3;
            }
            #pragma unroll
            for (int mt = 0; mt < 4; mt++)
                #pragma unroll
                for (int nt = 0; nt < 4; nt++)
                    mma_f16(acc[mt][nt], a[mt], b[nt]);
        }
    }

    // epilogue: bias add + float2 stores
    #pragma unroll
    for (int mt = 0; mt < 4; mt++) {
        const int row = m0 + warp_m * 64 + mt * 16 + grp;
        #pragma unroll
        for (int nt = 0; nt < 4; nt++) {
            const int col = n0 + warp_n * 32 + nt * 8 + tig * 2;
            const float2 cb = *(const float2*)(g_c + col);
            float2 v0, v1;
            v0.x = acc[mt][nt][0] + cb.x;
            v0.y = acc[mt][nt][1] + cb.y;
            v1.x = acc[mt][nt][2] + cb.x;
            v1.y = acc[mt][nt][3] + cb.y;
            *(float2*)(out + (size_t)row * DIMN + col) = v0;
            *(float2*)(out + (size_t)(row + 8) * DIMN + col) = v1;
        }
    }
}

// ---------------------------------------------------------------------------
// kernel_launch
// inputs: 0=x, 1=q_state, 2=Wq, 3=bq, 4=Wk, 5=bk, 6=Wv, 7=bv, 8=Wo, 9=bo
// ---------------------------------------------------------------------------
extern "C" void kernel_launch(void* const* d_in, const int* in_sizes, int n_in,
                              void* d_out, int out_size) {
    const float* x  = (const float*)d_in[0];
    const float* Wv = (const float*)d_in[6];
    const float* bv = (const float*)d_in[7];
    const float* Wo = (const float*)d_in[8];
    const float* bo = (const float*)d_in[9];
    float* out = (float*)d_out;

    conv_x_kernel<<<(NBATCH * DIMN) / (256 * 4), 256>>>(x);
    build_c_kernel<<<1, DIMN>>>(Wo, bv, bo);
    build_M_kernel<<<DIMN / 8, DIMN>>>(Wo, Wv);

    cudaFuncSetAttribute(gemm_f16_kernel,
                         cudaFuncAttributeMaxDynamicSharedMemorySize, GEMM_SMEM);
    gemm_f16_kernel<<<(NBATCH / BM) * (DIMN / BN), 256, GEMM_SMEM>>>(out);
}